// round 16
// baseline (speedup 1.0000x reference)
#include <cuda_runtime.h>
#include <math.h>

#define H      64
#define NFINE  (1 << 20)          // fine grid intervals over [0,1]
#define NC     (1 << 10)          // coarse grid intervals (= cubic cells)
#define NCTOT  (NC + 3)           // coarse entries: x = (idx-1)/NC
#define RSH    10                 // log2(NFINE/NC) = fine points per cell (1024)
#define UPC    1024               // fine points per cell
#define ZSH    12                 // log2(z-bucket count)
#define ZB     (1 << ZSH)         // z buckets -> 8 KB u16 map
#define MONO   1e-3f
#define SGRID  592                // search blocks: 4 per SM

__device__ float g_w2t[H * H];    // g_w2t[i*64+j] = exp(pw2[j][i])  (transposed)
__device__ float g_w1[H], g_b1[H], g_b2[H], g_w3[H], g_b3s;
__device__ float g_Ac[NCTOT];     // raw A at coarse grid (+/-1 pad)
// per-cell record, 32 B: [2c]={a,b,c,d} u-scaled; [2c+1]={-1/b, TS[c+1], 0, 0}
__device__ float4 g_CELL[NC * 2];
__device__ unsigned short g_map[ZB]; // z-bucket -> max cell c with TS[c] <= k/ZB

__device__ __forceinline__ float sigmoidf(float x) {
    return 1.0f / (1.0f + expf(-x));
}

// ---------------------------------------------------------------------------
// Kernel 0: one-shot weight prep -- exponentiate positivity-constrained
// weights, transpose w2 into global.
// ---------------------------------------------------------------------------
__global__ void prep_kernel(const float* __restrict__ pw1, const float* __restrict__ b1,
                            const float* __restrict__ pw2, const float* __restrict__ b2,
                            const float* __restrict__ pw3, const float* __restrict__ b3) {
    int e = blockIdx.x * blockDim.x + threadIdx.x;
    if (e < H * H) {
        int j = e >> 6, i = e & 63;
        g_w2t[i * H + j] = expf(pw2[e]);
    }
    if (e < H) {
        g_w1[e] = expf(pw1[e]);
        g_b1[e] = b1[e];
        g_b2[e] = b2[e];
        g_w3[e] = expf(pw3[e]);
    }
    if (e == 0) g_b3s = b3[0];
}

// ---------------------------------------------------------------------------
// Kernel 1: exact network eval A(x) on the coarse grid, ONE WARP PER POINT.
// ---------------------------------------------------------------------------
__global__ void coarse_kernel() {
    int gwarp = (blockIdx.x * blockDim.x + threadIdx.x) >> 5;
    int lane  = threadIdx.x & 31;
    if (gwarp >= NCTOT) return;
    float x = (float)(gwarp - 1) * (1.0f / (float)NC);

    float h1a = sigmoidf(fmaf(__ldg(&g_w1[lane]),      x, __ldg(&g_b1[lane])));
    float h1b = sigmoidf(fmaf(__ldg(&g_w1[lane + 32]), x, __ldg(&g_b1[lane + 32])));

    float acc0 = __ldg(&g_b2[2 * lane]);
    float acc1 = __ldg(&g_b2[2 * lane + 1]);
#pragma unroll
    for (int i = 0; i < 32; i++) {
        float  hv = __shfl_sync(0xffffffffu, h1a, i);
        float2 w  = __ldg(reinterpret_cast<const float2*>(&g_w2t[i * H + 2 * lane]));
        acc0 = fmaf(w.x, hv, acc0);
        acc1 = fmaf(w.y, hv, acc1);
    }
#pragma unroll
    for (int i = 0; i < 32; i++) {
        float  hv = __shfl_sync(0xffffffffu, h1b, i);
        float2 w  = __ldg(reinterpret_cast<const float2*>(&g_w2t[(i + 32) * H + 2 * lane]));
        acc0 = fmaf(w.x, hv, acc0);
        acc1 = fmaf(w.y, hv, acc1);
    }
    float part = fmaf(sigmoidf(acc0), __ldg(&g_w3[2 * lane]),
                      sigmoidf(acc1) * __ldg(&g_w3[2 * lane + 1]));
#pragma unroll
    for (int o = 16; o; o >>= 1) part += __shfl_xor_sync(0xffffffffu, part, o);

    if (lane == 0) g_Ac[gwarp] = sigmoidf(part + g_b3s) + MONO * x;
}

// ---------------------------------------------------------------------------
// Kernel 2: per-cell records + z-bucket map. u-units (t = u/1024; pow2
// divisions exact). TS[c+1] stored with bits identical to cell c+1's 'a'
// (same expression, same inputs). ceil-based runs tile [0, ZB) exactly.
// ---------------------------------------------------------------------------
__global__ void coeff_kernel() {
    int ci = blockIdx.x * blockDim.x + threadIdx.x;
    if (ci >= NC) return;
    const float a0      = g_Ac[1];
    const float a1      = g_Ac[1 + NC];
    const float inv_den = 1.0f / (a1 - a0);
    float P0 = g_Ac[ci];
    float P1 = g_Ac[ci + 1];
    float P2 = g_Ac[ci + 2];
    float P3 = g_Ac[ci + 3];
    float c1 = 0.5f * (P2 - P0);
    float c2 = P0 - 2.5f * P1 + 2.0f * P2 - 0.5f * P3;
    float c3 = 1.5f * (P1 - P2) + 0.5f * (P3 - P0);
    float a  = (P1 - a0) * inv_den;
    float bu = (c1 * inv_den) * (1.0f / 1024.0f);
    float cu = (c2 * inv_den) * (1.0f / 1048576.0f);
    float du = (c3 * inv_den) * (1.0f / 1073741824.0f);
    float tnext = (ci == NC - 1) ? 1.0f : (P2 - a0) * inv_den;

    g_CELL[2 * ci]     = make_float4(a, bu, cu, du);
    g_CELL[2 * ci + 1] = make_float4(-1.0f / bu, tnext, 0.0f, 0.0f);

    int k0 = (int)ceilf(a     * (float)ZB); // exact: pow2 scale
    int k1 = (int)ceilf(tnext * (float)ZB);
    if (k0 < 0) k0 = 0;
    if (k1 > ZB) k1 = ZB;
    for (int k = k0; k < k1; k++) g_map[k] = (unsigned short)ci;
}

// T at fine offset u within a cell (u-scaled coeffs): 3 FMA, bit-identical
// expression everywhere it is used.
__device__ __forceinline__ float horner_u(float4 cf, float u) {
    return fmaf(u, fmaf(u, fmaf(u, cf.w, cf.z), cf.y), cf.x);
}

// ---------------------------------------------------------------------------
// Kernel 3: persistent search with ALL tables in SHARED MEMORY (40 KB:
// 32 KB cell records + 8 KB u16 map). Banked smem serves the divergent
// per-lane lookups in a few phases instead of ~32 serialized L1tex
// wavefronts per warp-gather -- the measured bottleneck of R12-R15.
// Per z: u16 map LDS -> 32B record LDS -> rare advance (expected ~0.25
// compares) -> division-free 3-iter chord -> branch-free predicated +/-2
// corrections (pure FMA on in-register coeffs). Semantics:
// j = max{j : T(j) <= z} on the fine grid (fp32-noise +/-1 at seams,
// ~1e-6 output effect); out = (j + 0.5) * 2^-20.
// ---------------------------------------------------------------------------
__device__ __forceinline__ float invert_one_s(float zi, const float4* s_cell,
                                              const unsigned short* s_map) {
    int k = (int)(zi * (float)ZB);               // exact floor: pow2 scale
    k = min(max(k, 0), ZB - 1);
    int ci = (int)s_map[k];                      // TS[ci] <= k/ZB <= zi
    float4 ca = s_cell[2 * ci];
    float4 cb = s_cell[2 * ci + 1];
    while (cb.y <= zi) {                         // advance; tnext(NC-1)=1 > zi ends it
        ci++;
        ca = s_cell[2 * ci];
        cb = s_cell[2 * ci + 1];
    }
    float nrb = cb.x;                            // -1/b
    float u = (ca.x - zi) * nrb;                 // linear seed = (zi - a)/b
    u = fminf(fmaxf(u, 0.0f), 1024.0f);
#pragma unroll
    for (int it = 0; it < 3; it++)
        u = fmaf(horner_u(ca, u) - zi, nrb, u);  // u -= (T(u) - z)/b
    u = fminf(fmaxf(u, 0.0f), 1023.0f);          // NaN-safe
    int ui = (int)u;
    // predicated corrections (+/-2 window; T(0)=a <= zi keeps ui >= 0)
    ui -= (horner_u(ca, (float)ui) > zi);
    ui -= (horner_u(ca, (float)ui) > zi);
    ui += (horner_u(ca, (float)(ui + 1)) <= zi);
    ui += (horner_u(ca, (float)(ui + 1)) <= zi);
    ui = min(ui, UPC);
    int j = (ci << RSH) + ui;
    return (float)(2 * j + 1) * 0x1p-21f;        // (j + 0.5) * 2^-20, exact
}

__global__ void __launch_bounds__(256)
search_kernel(const float* __restrict__ z, float* __restrict__ out, int n) {
    __shared__ float4 s_cell[NC * 2];            // 32 KB
    __shared__ unsigned short s_map[ZB];         // 8 KB
    int tid = threadIdx.x;
    for (int idx = tid; idx < NC * 2; idx += 256) s_cell[idx] = g_CELL[idx];
    for (int idx = tid; idx < ZB / 2; idx += 256)
        reinterpret_cast<unsigned*>(s_map)[idx] =
            reinterpret_cast<const unsigned*>(g_map)[idx];
    __syncthreads();

    int nq = n >> 1;
    int stride = gridDim.x * blockDim.x;
    for (int p = blockIdx.x * blockDim.x + tid; p < nq; p += stride) {
        float2 zv = *reinterpret_cast<const float2*>(z + 2 * p);
        float2 ov;
        ov.x = invert_one_s(zv.x, s_cell, s_map);
        ov.y = invert_one_s(zv.y, s_cell, s_map);
        *reinterpret_cast<float2*>(out + 2 * p) = ov;
    }
    if ((n & 1) && blockIdx.x == 0 && tid == 0)
        out[n - 1] = invert_one_s(z[n - 1], s_cell, s_map);
}

// ---------------------------------------------------------------------------
extern "C" void kernel_launch(void* const* d_in, const int* in_sizes, int n_in,
                              void* d_out, int out_size) {
    const float* z   = (const float*)d_in[0];
    const float* pw1 = (const float*)d_in[1];
    const float* b1  = (const float*)d_in[2];
    const float* pw2 = (const float*)d_in[3];
    const float* b2  = (const float*)d_in[4];
    const float* pw3 = (const float*)d_in[5];
    const float* b3  = (const float*)d_in[6];
    float* out = (float*)d_out;
    int n = in_sizes[0];

    prep_kernel<<<(H * H + 255) / 256, 256>>>(pw1, b1, pw2, b2, pw3, b3);
    coarse_kernel<<<(NCTOT * 32 + 255) / 256, 256>>>();
    coeff_kernel<<<(NC + 255) / 256, 256>>>();
    search_kernel<<<SGRID, 256>>>(z, out, n);
}

// round 17
// speedup vs baseline: 1.1758x; 1.1758x over previous
#include <cuda_runtime.h>
#include <math.h>

#define H      64
#define NFINE  (1 << 20)          // fine grid intervals over [0,1]
#define NC     (1 << 11)          // coarse grid intervals (= cells)
#define NCTOT  (NC + 3)           // coarse entries: x = (idx-1)/NC
#define RSH    9                  // log2(NFINE/NC) = fine points per cell (512)
#define ZSH    14                 // log2(z-bucket count)
#define ZB     (1 << ZSH)         // z buckets -> 32 KB u16 map (L1-resident)
#define MONO   1e-3f

__device__ float g_w2t[H * H];    // g_w2t[i*64+j] = exp(pw2[j][i])  (transposed)
__device__ float g_w1[H], g_b1[H], g_b2[H], g_w3[H], g_b3s;
__device__ float g_Ac[NCTOT];     // raw A at coarse grid (+/-1 pad)
// per-cell record, ONE 16B load: {a, alpha, beta, -1/alpha}
// T^(s) = a + alpha*s + beta*s^2,  s = u/512, fit to cubic at s=0, 0.5, 1
__device__ float4 g_CF[NC];       // 32 KB
__device__ unsigned short g_map[ZB]; // z-bucket -> max cell c with a[c] <= k/ZB

__device__ __forceinline__ float sigmoidf(float x) {
    return 1.0f / (1.0f + expf(-x));
}

// ---------------------------------------------------------------------------
// Kernel 0: one-shot weight prep -- exponentiate positivity-constrained
// weights, transpose w2 into global.
// ---------------------------------------------------------------------------
__global__ void prep_kernel(const float* __restrict__ pw1, const float* __restrict__ b1,
                            const float* __restrict__ pw2, const float* __restrict__ b2,
                            const float* __restrict__ pw3, const float* __restrict__ b3) {
    int e = blockIdx.x * blockDim.x + threadIdx.x;
    if (e < H * H) {
        int j = e >> 6, i = e & 63;
        g_w2t[i * H + j] = expf(pw2[e]);
    }
    if (e < H) {
        g_w1[e] = expf(pw1[e]);
        g_b1[e] = b1[e];
        g_b2[e] = b2[e];
        g_w3[e] = expf(pw3[e]);
    }
    if (e == 0) g_b3s = b3[0];
}

// ---------------------------------------------------------------------------
// Kernel 1: exact network eval A(x) on the coarse grid, ONE WARP PER POINT.
// ---------------------------------------------------------------------------
__global__ void coarse_kernel() {
    int gwarp = (blockIdx.x * blockDim.x + threadIdx.x) >> 5;
    int lane  = threadIdx.x & 31;
    if (gwarp >= NCTOT) return;
    float x = (float)(gwarp - 1) * (1.0f / (float)NC);

    float h1a = sigmoidf(fmaf(__ldg(&g_w1[lane]),      x, __ldg(&g_b1[lane])));
    float h1b = sigmoidf(fmaf(__ldg(&g_w1[lane + 32]), x, __ldg(&g_b1[lane + 32])));

    float acc0 = __ldg(&g_b2[2 * lane]);
    float acc1 = __ldg(&g_b2[2 * lane + 1]);
#pragma unroll
    for (int i = 0; i < 32; i++) {
        float  hv = __shfl_sync(0xffffffffu, h1a, i);
        float2 w  = __ldg(reinterpret_cast<const float2*>(&g_w2t[i * H + 2 * lane]));
        acc0 = fmaf(w.x, hv, acc0);
        acc1 = fmaf(w.y, hv, acc1);
    }
#pragma unroll
    for (int i = 0; i < 32; i++) {
        float  hv = __shfl_sync(0xffffffffu, h1b, i);
        float2 w  = __ldg(reinterpret_cast<const float2*>(&g_w2t[(i + 32) * H + 2 * lane]));
        acc0 = fmaf(w.x, hv, acc0);
        acc1 = fmaf(w.y, hv, acc1);
    }
    float part = fmaf(sigmoidf(acc0), __ldg(&g_w3[2 * lane]),
                      sigmoidf(acc1) * __ldg(&g_w3[2 * lane + 1]));
#pragma unroll
    for (int o = 16; o; o >>= 1) part += __shfl_xor_sync(0xffffffffu, part, o);

    if (lane == 0) g_Ac[gwarp] = sigmoidf(part + g_b3s) + MONO * x;
}

// ---------------------------------------------------------------------------
// Kernel 2: per-cell quadratic records + z-bucket map. The quadratic is fit
// to the Catmull-Rom cubic at s = 0, 0.5, 1: T^(0) = a (exact expression,
// matching the map construction) and T^(1) = a + alpha + beta = tnext
// (within 1-2 ulp; seam mismatches resolve through the ui=-1/513 correction
// paths). Deviation from the cubic <= |c3n|/4 ~ 0.03 fine steps. ceil-based
// runs tile [0, ZB) exactly (pow2 scale => exact arithmetic; T monotone in
// fp32 since A gains >= MONO/NC ~ 4.9e-7 per cell >> fp32 eps).
// ---------------------------------------------------------------------------
__global__ void coeff_kernel() {
    int ci = blockIdx.x * blockDim.x + threadIdx.x;
    if (ci >= NC) return;
    const float a0      = g_Ac[1];
    const float a1      = g_Ac[1 + NC];
    const float inv_den = 1.0f / (a1 - a0);
    float P0 = g_Ac[ci];
    float P1 = g_Ac[ci + 1];
    float P2 = g_Ac[ci + 2];
    float P3 = g_Ac[ci + 3];
    float c1 = 0.5f * (P2 - P0);
    float c2 = P0 - 2.5f * P1 + 2.0f * P2 - 0.5f * P3;
    float c3 = 1.5f * (P1 - P2) + 0.5f * (P3 - P0);
    float c1n = c1 * inv_den, c2n = c2 * inv_den, c3n = c3 * inv_den;

    float a     = (P1 - a0) * inv_den;               // cell 0 -> exactly 0.0f
    float tnext = (ci == NC - 1) ? 1.0f : (P2 - a0) * inv_den;
    float D     = tnext - a;
    float m     = fmaf(0.125f, c3n, fmaf(0.25f, c2n, 0.5f * c1n)); // Tmid - a
    float alpha = fmaf(4.0f, m, -D);
    float beta  = D - alpha;

    g_CF[ci] = make_float4(a, alpha, beta, -1.0f / alpha);

    int k0 = (int)ceilf(a     * (float)ZB);          // exact: pow2 scale
    int k1 = (int)ceilf(tnext * (float)ZB);
    if (k0 < 0) k0 = 0;
    if (k1 > ZB) k1 = ZB;
    for (int k = k0; k < k1; k++) g_map[k] = (unsigned short)ci;
}

// quadratic T^ at s (2 FMA), bit-identical expression everywhere
__device__ __forceinline__ float quadT(float4 cf, float s) {
    return fmaf(s, fmaf(s, cf.z, cf.y), cf.x);
}

// ---------------------------------------------------------------------------
// Kernel 3: per-target inversion -- minimal serial chain: ~35 inst and TWO
// loads per z (u16 map + ONE 16B cell record; R13 needed four). Advance
// test is the in-register compare a+alpha+beta <= z (bit-consistent with
// map boundaries). Division-free 2-iter chord in s-space (slope varies
// ~0.5% within a cell -> residual << 1 step), floor, then ONE down + ONE up
// predicated correction; ui may legally become -1 (seam: answer is the
// previous cell's last step) or 513. Semantics: j = max{j : T(j) <= z} on
// the fine grid (fp32-noise +/-1 at seams, ~1e-6 output effect);
// out = (j + 0.5) * 2^-20, j clamped to [0, NFINE-1].
// ---------------------------------------------------------------------------
__device__ __forceinline__ float invert_one(float zi) {
    int k = (int)(zi * (float)ZB);               // exact floor: pow2 scale
    k = min(max(k, 0), ZB - 1);
    int ci = (int)__ldg(&g_map[k]);              // a[ci] <= k/ZB <= zi
    float4 cf = __ldg(&g_CF[ci]);
    while (ci < NC - 1 && (cf.x + cf.y + cf.z) <= zi) {  // T^(1) <= z: advance
        ci++;
        cf = __ldg(&g_CF[ci]);
    }
    float nra = cf.w;                            // -1/alpha
    float s = (cf.x - zi) * nra;                 // linear seed = (z - a)/alpha
    s = fminf(fmaxf(s, 0.0f), 1.0f);
#pragma unroll
    for (int it = 0; it < 2; it++)
        s = fmaf(quadT(cf, s) - zi, nra, s);     // s -= (T^(s) - z)/alpha
    s = fminf(fmaxf(s, 0.0f), 1.0f);             // NaN-safe
    int ui = (int)(s * 512.0f);
    ui = min(ui, 512);
    // one predicated correction each way (su, sv exact: pow2 divide)
    float su = (float)ui * (1.0f / 512.0f);
    ui -= (quadT(cf, su) > zi);                  // may take ui to -1 (seam)
    float sv = (float)(ui + 1) * (1.0f / 512.0f);
    ui += (quadT(cf, sv) <= zi);
    int j = (ci << RSH) + ui;
    j = min(max(j, 0), NFINE - 1);
    return (float)(2 * j + 1) * 0x1p-21f;        // (j + 0.5) * 2^-20, exact
}

__global__ void search_kernel(const float* __restrict__ z, float* __restrict__ out, int n) {
    int i = (blockIdx.x * blockDim.x + threadIdx.x) * 2;
    if (i + 1 < n) {
        float2 zv = *reinterpret_cast<const float2*>(z + i);
        float2 ov;
        ov.x = invert_one(zv.x);
        ov.y = invert_one(zv.y);
        *reinterpret_cast<float2*>(out + i) = ov;
    } else if (i < n) {
        out[i] = invert_one(z[i]);
    }
}

// ---------------------------------------------------------------------------
extern "C" void kernel_launch(void* const* d_in, const int* in_sizes, int n_in,
                              void* d_out, int out_size) {
    const float* z   = (const float*)d_in[0];
    const float* pw1 = (const float*)d_in[1];
    const float* b1  = (const float*)d_in[2];
    const float* pw2 = (const float*)d_in[3];
    const float* b2  = (const float*)d_in[4];
    const float* pw3 = (const float*)d_in[5];
    const float* b3  = (const float*)d_in[6];
    float* out = (float*)d_out;
    int n = in_sizes[0];

    prep_kernel<<<(H * H + 255) / 256, 256>>>(pw1, b1, pw2, b2, pw3, b3);
    coarse_kernel<<<(NCTOT * 32 + 255) / 256, 256>>>();
    coeff_kernel<<<(NC + 255) / 256, 256>>>();
    int nq = (n + 1) / 2;
    search_kernel<<<(nq + 255) / 256, 256>>>(z, out, n);
}